// round 11
// baseline (speedup 1.0000x reference)
#include <cuda_runtime.h>
#include <math.h>

#define NB   16
#define SL   128
#define NN   2048
#define HH   256
#define LOUT 12
#define NLEV 21
#define GRID 128

__device__ float g_x[NN * 256];
__device__ float g_proj[NN * 1024];
__device__ float g_h[NN * 256];
__device__ float g_c[NN * 256];
__device__ float g_wT[4 * 256 * 256];   // [m][ch][d]: 0=Wih 1=Woh 2=Wuh 3=Wfh (transposed)
__device__ int   g_coff[NB][SL + 1];
__device__ int   g_cch[NB][SL];
__device__ int   g_loff[NB][NLEV + 2];
__device__ int   g_lnode[NB][SL];
__device__ unsigned g_tbar[NB][NLEV + 1];
__device__ unsigned g_gbar[4];

__device__ __forceinline__ float sg(float v) { return 1.0f / (1.0f + __expf(-v)); }

__device__ __forceinline__ void bar_sig(unsigned* p) {
    unsigned long long ga;
    asm("cvta.to.global.u64 %0, %1;" : "=l"(ga) : "l"(p));
    asm volatile("red.release.gpu.global.add.u32 [%0], 1;" :: "l"(ga) : "memory");
}
__device__ __forceinline__ void bar_spin(unsigned* p, unsigned tgt) {
    unsigned long long ga;
    asm("cvta.to.global.u64 %0, %1;" : "=l"(ga) : "l"(p));
    unsigned v;
    do {
        asm volatile("ld.acquire.gpu.global.u32 %0, [%1];" : "=r"(v) : "l"(ga) : "memory");
    } while (v < tgt);
}

__global__ void k_zero() {
    int t = threadIdx.x;
    if (t < NB * (NLEV + 1)) ((unsigned*)g_tbar)[t] = 0u;
    if (t < 4) g_gbar[t] = 0u;
}

__global__ void __launch_bounds__(256) k_main(
    const int* __restrict__ xs, const int* __restrict__ rels,
    const int* __restrict__ parent, const int* __restrict__ height,
    const float* __restrict__ embW, const float* __restrict__ relW,
    const float* __restrict__ Wix, const float* __restrict__ bix,
    const float* __restrict__ Wih, const float* __restrict__ bih,
    const float* __restrict__ Wfx, const float* __restrict__ bfx,
    const float* __restrict__ Wfh, const float* __restrict__ bfh,
    const float* __restrict__ Wox, const float* __restrict__ Woh,
    const float* __restrict__ Wux, const float* __restrict__ Wuh,
    const float* __restrict__ Wout, const float* __restrict__ bout,
    float* __restrict__ out)
{
    __shared__ __align__(16) float sm[5120];   // 20 KB, reused per phase
    int tid = threadIdx.x;
    int bx = blockIdx.x;

    // ========== phase 1: gather x = concat(emb[xs], rel[rels]) ==========
    for (int idx = tid; idx < 16 * 256; idx += 256) {
        int nl = idx >> 8, d = idx & 255;
        int n = bx * 16 + nl;
        float v = (d < 192) ? embW[(long long)xs[n] * 192 + d]
                            : relW[(long long)rels[n] * 64 + (d - 192)];
        g_x[n * 256 + d] = v;
    }

    // ========== phase 2: setup (CTAs 0..15, deterministic) ==========
    if (bx < NB) {
        int b = bx;
        int* spar  = (int*)sm;            // [128]
        int* shgt  = spar + 128;          // [128]
        int* soff  = shgt + 128;          // [129]
        int* sloff = soff + 129;          // [23]
        if (tid < 127) spar[tid] = parent[b * 127 + tid] - b * 128;
        if (tid < 128) shgt[tid] = height[b * 128 + tid];
        __syncthreads();
        if (tid < 128) {
            int d = 0;
            for (int e = 0; e < 127; e++) d += (spar[e] == tid);
            soff[tid] = d;
        }
        __syncthreads();
        if (tid == 0) {
            int acc = 0;
            for (int i = 0; i < 128; i++) {
                int d = soff[i]; soff[i] = acc; g_coff[b][i] = acc; acc += d;
            }
            soff[128] = acc; g_coff[b][128] = acc;
        }
        __syncthreads();
        if (tid < 128) {
            int k = soff[tid];
            for (int e = 0; e < 127; e++)
                if (spar[e] == tid) g_cch[b][k++] = e + 1;
        }
        if (tid <= NLEV) {
            int c = 0;
            for (int i = 0; i < 128; i++) c += (shgt[i] == tid);
            sloff[tid] = c;
        }
        __syncthreads();
        if (tid == 0) {
            int acc = 0;
            for (int l = 0; l <= NLEV; l++) {
                int c = sloff[l]; sloff[l] = acc; g_loff[b][l] = acc; acc += c;
            }
            g_loff[b][NLEV + 1] = acc;
        }
        __syncthreads();
        if (tid < 128) {
            int h = shgt[tid];
            int rank = 0;
            for (int i = 0; i < tid; i++) rank += (shgt[i] == h);
            g_lnode[b][sloff[h] + rank] = tid;
        }
    }
    __syncthreads();   // smem handoff (setup -> transpose)

    // ========== phase 2.5: transpose recurrent weights into g_wT[m][ch][d] ==========
    {
        int r8 = tid >> 5, c32 = tid & 31;
        for (int tile = bx; tile < 256; tile += GRID) {
            int m = tile >> 6, rem = tile & 63, ti = rem >> 3, tj = rem & 7;
            const float* W = (m == 0) ? Wih : (m == 1) ? Woh : (m == 2) ? Wuh : Wfh;
#pragma unroll
            for (int p = 0; p < 4; p++) {
                int row = p * 8 + r8;   // d-local
                sm[row * 33 + c32] = W[(ti * 32 + row) * 256 + tj * 32 + c32];
            }
            __syncthreads();
#pragma unroll
            for (int p = 0; p < 4; p++) {
                int orow = p * 8 + r8;  // ch-local
                g_wT[m * 65536 + (tj * 32 + orow) * 256 + ti * 32 + c32] = sm[c32 * 33 + orow];
            }
            __syncthreads();
        }
    }
    // ---- grid barrier 0 (gather + setup visible) ----
    __syncthreads();
    if (tid == 0) { bar_sig(&g_gbar[0]); bar_spin(&g_gbar[0], GRID); }
    __syncthreads();

    // ========== phase 3: projections GEMM ==========
    {
        float* As = sm;            // [16][65]
        float* Bs = As + 16 * 65;  // [16][64]
        int tx = tid & 15, ty = tid >> 4;
        for (int tile = bx; tile < 512; tile += GRID) {
            int n0 = (tile & 31) * 64;
            int j0 = (tile >> 5) * 64;
            int m = j0 >> 8, h0 = j0 & 255;
            const float* W = (m == 0) ? Wix : (m == 1) ? Wfx : (m == 2) ? Wox : Wux;
            float acc[4][4];
#pragma unroll
            for (int i = 0; i < 4; i++)
#pragma unroll
                for (int j = 0; j < 4; j++) acc[i][j] = 0.0f;
            for (int k0 = 0; k0 < 256; k0 += 16) {
                for (int e = tid; e < 1024; e += 256) {
                    int nl = e >> 4, kk = e & 15;
                    As[kk * 65 + nl] = g_x[(n0 + nl) * 256 + k0 + kk];
                }
                for (int e = tid; e < 1024; e += 256) {
                    int kk = e >> 6, c = e & 63;
                    Bs[kk * 64 + c] = W[(k0 + kk) * 256 + h0 + c];
                }
                __syncthreads();
#pragma unroll
                for (int kk = 0; kk < 16; kk++) {
                    float a0 = As[kk * 65 + tx * 4 + 0], a1 = As[kk * 65 + tx * 4 + 1];
                    float a2 = As[kk * 65 + tx * 4 + 2], a3 = As[kk * 65 + tx * 4 + 3];
                    float b0 = Bs[kk * 64 + ty * 4 + 0], b1 = Bs[kk * 64 + ty * 4 + 1];
                    float b2 = Bs[kk * 64 + ty * 4 + 2], b3 = Bs[kk * 64 + ty * 4 + 3];
                    acc[0][0] += a0 * b0; acc[0][1] += a0 * b1; acc[0][2] += a0 * b2; acc[0][3] += a0 * b3;
                    acc[1][0] += a1 * b0; acc[1][1] += a1 * b1; acc[1][2] += a1 * b2; acc[1][3] += a1 * b3;
                    acc[2][0] += a2 * b0; acc[2][1] += a2 * b1; acc[2][2] += a2 * b2; acc[2][3] += a2 * b3;
                    acc[3][0] += a3 * b0; acc[3][1] += a3 * b1; acc[3][2] += a3 * b2; acc[3][3] += a3 * b3;
                }
                __syncthreads();
            }
#pragma unroll
            for (int jj = 0; jj < 4; jj++) {
                int h = h0 + ty * 4 + jj;
                float bias = (m == 0) ? (bix[h] + bih[h]) : (m == 1) ? (bfx[h] + bfh[h]) : 0.0f;
                int j = j0 + ty * 4 + jj;
#pragma unroll
                for (int i = 0; i < 4; i++)
                    g_proj[(n0 + tx * 4 + i) * 1024 + j] = acc[i][jj] + bias;
            }
        }
    }
    // ---- grid barrier 1 (proj visible) ----
    __syncthreads();
    if (tid == 0) { bar_sig(&g_gbar[1]); bar_spin(&g_gbar[1], GRID); }
    __syncthreads();

    // ========== phase 4: tree LSTM (8 CTAs/tree, 32 channels each) ==========
    {
        int b = bx >> 3, q = bx & 7, ch0 = q * 32;
        int w = tid >> 5, l = tid & 31;
        int ch = ch0 + l;
        float* hsum  = sm;           // [256]
        float* spart = sm + 256;     // [3][8][32]
        float* swfhh = sm + 1024;    // [128][32] per-CTA WfhH slice cache

        // ----- level 0: leaves, pure elementwise -----
        {
            int lb = g_loff[b][0], le = g_loff[b][1];
            for (int li = lb + w; li < le; li += 8) {
                int n = (b << 7) + g_lnode[b][li];
                const float* pr = g_proj + (size_t)n * 1024;
                float i = sg(pr[ch]), o = sg(pr[512 + ch]), u = tanhf(pr[768 + ch]);
                float c = i * u;
                g_c[(size_t)n * 256 + ch] = c;
                g_h[(size_t)n * 256 + ch] = o * tanhf(c);
            }
        }
        __syncthreads();
        if (tid == 0) { bar_sig(&g_tbar[b][0]); bar_spin(&g_tbar[b][0], 8u); }
        __syncthreads();

        for (int L = 1; L <= 20; L++) {
            // ----- A: WfhH slice for nodes committed at L-1 (warp-per-node) -----
            int pb = g_loff[b][L - 1], pe = g_loff[b][L];
            for (int li = pb + w; li < pe; li += 8) {
                int loc = g_lnode[b][li];
                const float4* hp = (const float4*)(g_h + (size_t)((b << 7) + loc) * 256);
                const float4* wt = (const float4*)(g_wT + 3 * 65536 + ch * 256);
                float a0 = 0, a1 = 0, a2 = 0, a3 = 0;
#pragma unroll 8
                for (int d4 = 0; d4 < 64; d4++) {
                    float4 h4 = hp[d4];       // broadcast across warp
                    float4 w4 = wt[d4];       // LDG.128, per-lane row
                    a0 = fmaf(h4.x, w4.x, a0); a1 = fmaf(h4.y, w4.y, a1);
                    a2 = fmaf(h4.z, w4.z, a2); a3 = fmaf(h4.w, w4.w, a3);
                }
                swfhh[loc * 32 + l] = (a0 + a1) + (a2 + a3);
            }
            __syncthreads();

            // ----- B: commit height-L nodes (whole CTA per node, d split over warps) -----
            int nbeg = g_loff[b][L], nend = g_loff[b][L + 1];
            for (int ni = nbeg; ni < nend; ni++) {
                int loc = g_lnode[b][ni];
                int n = (b << 7) + loc;
                int beg = g_coff[b][loc], end = g_coff[b][loc + 1];
                float s = 0.0f;                       // h_sum: thread tid = dim d
                for (int e = beg; e < end; e++)
                    s += g_h[(size_t)((b << 7) + g_cch[b][e]) * 256 + tid];
                hsum[tid] = s;
                __syncthreads();

                const float4* hs4 = (const float4*)(hsum + w * 32);
                const float4* wi4 = (const float4*)(g_wT + 0 * 65536 + ch * 256 + w * 32);
                const float4* wo4 = (const float4*)(g_wT + 1 * 65536 + ch * 256 + w * 32);
                const float4* wu4 = (const float4*)(g_wT + 2 * 65536 + ch * 256 + w * 32);
                float i0 = 0, i1 = 0, i2 = 0, i3 = 0;
                float o0 = 0, o1 = 0, o2 = 0, o3 = 0;
                float u0 = 0, u1 = 0, u2 = 0, u3 = 0;
#pragma unroll
                for (int d4 = 0; d4 < 8; d4++) {
                    float4 h4 = hs4[d4];
                    float4 wa = wi4[d4];
                    i0 = fmaf(h4.x, wa.x, i0); i1 = fmaf(h4.y, wa.y, i1);
                    i2 = fmaf(h4.z, wa.z, i2); i3 = fmaf(h4.w, wa.w, i3);
                    float4 wb = wo4[d4];
                    o0 = fmaf(h4.x, wb.x, o0); o1 = fmaf(h4.y, wb.y, o1);
                    o2 = fmaf(h4.z, wb.z, o2); o3 = fmaf(h4.w, wb.w, o3);
                    float4 wc = wu4[d4];
                    u0 = fmaf(h4.x, wc.x, u0); u1 = fmaf(h4.y, wc.y, u1);
                    u2 = fmaf(h4.z, wc.z, u2); u3 = fmaf(h4.w, wc.w, u3);
                }
                spart[      w * 32 + l] = (i0 + i1) + (i2 + i3);
                spart[256 + w * 32 + l] = (o0 + o1) + (o2 + o3);
                spart[512 + w * 32 + l] = (u0 + u1) + (u2 + u3);
                __syncthreads();

                if (w == 0) {
                    float ai = 0, ao = 0, au = 0;
#pragma unroll
                    for (int ww = 0; ww < 8; ww++) {
                        ai += spart[ww * 32 + l];
                        ao += spart[256 + ww * 32 + l];
                        au += spart[512 + ww * 32 + l];
                    }
                    const float* pr = g_proj + (size_t)n * 1024;
                    float fxv = pr[256 + ch];
                    float fc = 0.0f;
                    for (int e = beg; e < end; e++) {
                        int cl = g_cch[b][e];
                        fc = fmaf(sg(swfhh[cl * 32 + l] + fxv),
                                  g_c[(size_t)((b << 7) + cl) * 256 + ch], fc);
                    }
                    float ig = sg(pr[ch] + ai);
                    float og = sg(pr[512 + ch] + ao);
                    float ug = tanhf(pr[768 + ch] + au);
                    float cc = fmaf(ig, ug, fc);
                    g_c[(size_t)n * 256 + ch] = cc;
                    g_h[(size_t)n * 256 + ch] = og * tanhf(cc);
                }
                __syncthreads();
            }
            if (tid == 0) { bar_sig(&g_tbar[b][L]); bar_spin(&g_tbar[b][L], 8u); }
            __syncthreads();
        }

        // ----- fused max-pool + output projection (CTA q==0 of each tree) -----
        if (q == 0) {
            float m = -1e30f;
            const float* hp = g_h + (size_t)(b << 7) * 256 + tid;
#pragma unroll 4
            for (int s = 0; s < 128; s++) m = fmaxf(m, hp[s * 256]);
            sm[tid] = m;
            __syncthreads();
            if (tid < LOUT) {
                float a = bout[tid];
#pragma unroll 8
                for (int d = 0; d < 256; d++) a = fmaf(sm[d], Wout[d * LOUT + tid], a);
                out[b * LOUT + tid] = a;
            }
        }
    }
}

extern "C" void kernel_launch(void* const* d_in, const int* in_sizes, int n_in,
                              void* d_out, int out_size) {
    const int* xs     = (const int*)d_in[0];
    const int* rels   = (const int*)d_in[1];
    const int* parent = (const int*)d_in[3];
    const int* height = (const int*)d_in[4];
    int base = (in_sizes[5] == 1) ? 6 : 5;
    const float* embW = (const float*)d_in[base + 0];
    const float* relW = (const float*)d_in[base + 1];
    const float* Wix  = (const float*)d_in[base + 2];
    const float* bix  = (const float*)d_in[base + 3];
    const float* Wih  = (const float*)d_in[base + 4];
    const float* bih  = (const float*)d_in[base + 5];
    const float* Wfx  = (const float*)d_in[base + 6];
    const float* bfx  = (const float*)d_in[base + 7];
    const float* Wfh  = (const float*)d_in[base + 8];
    const float* bfh  = (const float*)d_in[base + 9];
    const float* Wox  = (const float*)d_in[base + 10];
    const float* Woh  = (const float*)d_in[base + 11];
    const float* Wux  = (const float*)d_in[base + 12];
    const float* Wuh  = (const float*)d_in[base + 13];
    const float* Wout = (const float*)d_in[base + 14];
    const float* bout = (const float*)d_in[base + 15];
    float* out = (float*)d_out;

    k_zero<<<1, 512>>>();
    k_main<<<GRID, 256>>>(xs, rels, parent, height, embW, relW,
                          Wix, bix, Wih, bih, Wfx, bfx, Wfh, bfh,
                          Wox, Woh, Wux, Wuh, Wout, bout, out);
}

// round 12
// speedup vs baseline: 1.7665x; 1.7665x over previous
#include <cuda_runtime.h>
#include <math.h>

#define NB   16
#define SL   128
#define NN   2048
#define HH   256
#define LOUT 12
#define NLEV 21
#define GRID 128

__device__ float g_x[NN * 256];
__device__ float g_proj[NN * 1024];
__device__ float g_h[NN * 256];
__device__ float g_c[NN * 256];
__device__ int   g_coff[NB][SL + 1];
__device__ int   g_cch[NB][SL];
__device__ int   g_loff[NB][NLEV + 2];
__device__ int   g_lnode[NB][SL];
__device__ unsigned g_tbar[NB][NLEV + 1];
__device__ unsigned g_gbar[4];

__device__ __forceinline__ float sg(float v) { return 1.0f / (1.0f + __expf(-v)); }

__device__ __forceinline__ void bar_sig(unsigned* p) {
    unsigned long long ga;
    asm("cvta.to.global.u64 %0, %1;" : "=l"(ga) : "l"(p));
    asm volatile("red.release.gpu.global.add.u32 [%0], 1;" :: "l"(ga) : "memory");
}
__device__ __forceinline__ void bar_spin(unsigned* p, unsigned tgt) {
    unsigned long long ga;
    asm("cvta.to.global.u64 %0, %1;" : "=l"(ga) : "l"(p));
    unsigned v;
    do {
        asm volatile("ld.acquire.gpu.global.u32 %0, [%1];" : "=r"(v) : "l"(ga) : "memory");
    } while (v < tgt);
}

__global__ void k_zero() {
    int t = threadIdx.x;
    if (t < NB * (NLEV + 1)) ((unsigned*)g_tbar)[t] = 0u;
    if (t < 4) g_gbar[t] = 0u;
}

// smem float offsets (phase 4)
#define SWFHH 0        // [128][32]
#define SHST  4096     // 8 warps x 264
#define SHSUM 6208     // [256]
#define SPART 6464     // [3][256]
#define SPARTA 7232    // [2][8][32]

__global__ void __launch_bounds__(256) k_main(
    const int* __restrict__ xs, const int* __restrict__ rels,
    const int* __restrict__ parent, const int* __restrict__ height,
    const float* __restrict__ embW, const float* __restrict__ relW,
    const float* __restrict__ Wix, const float* __restrict__ bix,
    const float* __restrict__ Wih, const float* __restrict__ bih,
    const float* __restrict__ Wfx, const float* __restrict__ bfx,
    const float* __restrict__ Wfh, const float* __restrict__ bfh,
    const float* __restrict__ Wox, const float* __restrict__ Woh,
    const float* __restrict__ Wux, const float* __restrict__ Wuh,
    const float* __restrict__ Wout, const float* __restrict__ bout,
    float* __restrict__ out)
{
    __shared__ __align__(16) float sm[7808];
    int tid = threadIdx.x;
    int bx = blockIdx.x;

    // ========== phase 1: gather x = concat(emb[xs], rel[rels]) ==========
    for (int idx = tid; idx < 16 * 256; idx += 256) {
        int nl = idx >> 8, d = idx & 255;
        int n = bx * 16 + nl;
        float v = (d < 192) ? embW[(long long)xs[n] * 192 + d]
                            : relW[(long long)rels[n] * 64 + (d - 192)];
        g_x[n * 256 + d] = v;
    }

    // ========== phase 2: setup (CTAs 0..15, deterministic) ==========
    if (bx < NB) {
        int b = bx;
        int* spar  = (int*)sm;            // [128]
        int* shgt  = spar + 128;          // [128]
        int* soff  = shgt + 128;          // [129]
        int* sloff = soff + 129;          // [23]
        if (tid < 127) spar[tid] = parent[b * 127 + tid] - b * 128;
        if (tid < 128) shgt[tid] = height[b * 128 + tid];
        __syncthreads();
        if (tid < 128) {
            int d = 0;
            for (int e = 0; e < 127; e++) d += (spar[e] == tid);
            soff[tid] = d;
        }
        __syncthreads();
        if (tid == 0) {
            int acc = 0;
            for (int i = 0; i < 128; i++) {
                int d = soff[i]; soff[i] = acc; g_coff[b][i] = acc; acc += d;
            }
            soff[128] = acc; g_coff[b][128] = acc;
        }
        __syncthreads();
        if (tid < 128) {
            int k = soff[tid];
            for (int e = 0; e < 127; e++)
                if (spar[e] == tid) g_cch[b][k++] = e + 1;
        }
        if (tid <= NLEV) {
            int c = 0;
            for (int i = 0; i < 128; i++) c += (shgt[i] == tid);
            sloff[tid] = c;
        }
        __syncthreads();
        if (tid == 0) {
            int acc = 0;
            for (int l = 0; l <= NLEV; l++) {
                int c = sloff[l]; sloff[l] = acc; g_loff[b][l] = acc; acc += c;
            }
            g_loff[b][NLEV + 1] = acc;
        }
        __syncthreads();
        if (tid < 128) {
            int h = shgt[tid];
            int rank = 0;
            for (int i = 0; i < tid; i++) rank += (shgt[i] == h);
            g_lnode[b][sloff[h] + rank] = tid;
        }
    }
    // ---- grid barrier 0 ----
    __syncthreads();
    if (tid == 0) { bar_sig(&g_gbar[0]); bar_spin(&g_gbar[0], GRID); }
    __syncthreads();

    // ========== phase 3: projections GEMM ==========
    {
        float* As = sm;            // [16][65]
        float* Bs = As + 16 * 65;  // [16][64]
        int tx = tid & 15, ty = tid >> 4;
        for (int tile = bx; tile < 512; tile += GRID) {
            int n0 = (tile & 31) * 64;
            int j0 = (tile >> 5) * 64;
            int m = j0 >> 8, h0 = j0 & 255;
            const float* W = (m == 0) ? Wix : (m == 1) ? Wfx : (m == 2) ? Wox : Wux;
            float acc[4][4];
#pragma unroll
            for (int i = 0; i < 4; i++)
#pragma unroll
                for (int j = 0; j < 4; j++) acc[i][j] = 0.0f;
            for (int k0 = 0; k0 < 256; k0 += 16) {
                for (int e = tid; e < 1024; e += 256) {
                    int nl = e >> 4, kk = e & 15;
                    As[kk * 65 + nl] = g_x[(n0 + nl) * 256 + k0 + kk];
                }
                for (int e = tid; e < 1024; e += 256) {
                    int kk = e >> 6, c = e & 63;
                    Bs[kk * 64 + c] = W[(k0 + kk) * 256 + h0 + c];
                }
                __syncthreads();
#pragma unroll
                for (int kk = 0; kk < 16; kk++) {
                    float a0 = As[kk * 65 + tx * 4 + 0], a1 = As[kk * 65 + tx * 4 + 1];
                    float a2 = As[kk * 65 + tx * 4 + 2], a3 = As[kk * 65 + tx * 4 + 3];
                    float b0 = Bs[kk * 64 + ty * 4 + 0], b1 = Bs[kk * 64 + ty * 4 + 1];
                    float b2 = Bs[kk * 64 + ty * 4 + 2], b3 = Bs[kk * 64 + ty * 4 + 3];
                    acc[0][0] += a0 * b0; acc[0][1] += a0 * b1; acc[0][2] += a0 * b2; acc[0][3] += a0 * b3;
                    acc[1][0] += a1 * b0; acc[1][1] += a1 * b1; acc[1][2] += a1 * b2; acc[1][3] += a1 * b3;
                    acc[2][0] += a2 * b0; acc[2][1] += a2 * b1; acc[2][2] += a2 * b2; acc[2][3] += a2 * b3;
                    acc[3][0] += a3 * b0; acc[3][1] += a3 * b1; acc[3][2] += a3 * b2; acc[3][3] += a3 * b3;
                }
                __syncthreads();
            }
#pragma unroll
            for (int jj = 0; jj < 4; jj++) {
                int h = h0 + ty * 4 + jj;
                float bias = (m == 0) ? (bix[h] + bih[h]) : (m == 1) ? (bfx[h] + bfh[h]) : 0.0f;
                int j = j0 + ty * 4 + jj;
#pragma unroll
                for (int i = 0; i < 4; i++)
                    g_proj[(n0 + tx * 4 + i) * 1024 + j] = acc[i][jj] + bias;
            }
        }
    }
    // ---- grid barrier 1 ----
    __syncthreads();
    if (tid == 0) { bar_sig(&g_gbar[1]); bar_spin(&g_gbar[1], GRID); }
    __syncthreads();

    // ========== phase 4: tree LSTM (8 CTAs/tree, 32 channels each) ==========
    {
        int b = bx >> 3, q = bx & 7, ch0 = q * 32;
        int w = tid >> 5, l = tid & 31;
        int ch = ch0 + l;
        float* swfhh = sm + SWFHH;
        float* shw   = sm + SHST + w * 264;   // per-warp h staging
        float* hsum  = sm + SHSUM;
        float* spart = sm + SPART;
        float* sparta = sm + SPARTA;

        // ----- level 0: leaves (elementwise) -----
        {
            int lb = g_loff[b][0], le = g_loff[b][1];
            for (int li = lb + w; li < le; li += 8) {
                int n = (b << 7) + g_lnode[b][li];
                const float* pr = g_proj + (size_t)n * 1024;
                float i = sg(pr[ch]), o = sg(pr[512 + ch]), u = tanhf(pr[768 + ch]);
                float c = i * u;
                g_c[(size_t)n * 256 + ch] = c;
                g_h[(size_t)n * 256 + ch] = o * tanhf(c);
            }
        }
        __syncthreads();
        if (tid == 0) { bar_sig(&g_tbar[b][0]); bar_spin(&g_tbar[b][0], 8u); }
        __syncthreads();

        for (int L = 1; L <= 20; L++) {
            // ===== phase A: Wfh·h slice for nodes committed at L-1 =====
            int pb = g_loff[b][L - 1], pe = g_loff[b][L];
            int cA = pe - pb;
            if (cA > 2) {
                // warp-per-node, h staged in smem, coalesced Wfh reads
                for (int li = pb + w; li < pe; li += 8) {
                    int loc = g_lnode[b][li];
                    const float* hv = g_h + (size_t)((b << 7) + loc) * 256;
#pragma unroll
                    for (int k = 0; k < 8; k++) shw[l + 32 * k] = hv[l + 32 * k];
                    __syncwarp();
                    float a0 = 0, a1 = 0, a2 = 0, a3 = 0;
#pragma unroll 4
                    for (int d = 0; d < 256; d += 4) {
                        a0 = fmaf(shw[d + 0], Wfh[(d + 0) * 256 + ch], a0);
                        a1 = fmaf(shw[d + 1], Wfh[(d + 1) * 256 + ch], a1);
                        a2 = fmaf(shw[d + 2], Wfh[(d + 2) * 256 + ch], a2);
                        a3 = fmaf(shw[d + 3], Wfh[(d + 3) * 256 + ch], a3);
                    }
                    swfhh[loc * 32 + l] = (a0 + a1) + (a2 + a3);
                    __syncwarp();
                }
            } else if (cA > 0) {
                // narrow: split d over warps
                int chunks = (cA == 2) ? 4 : 8;
                int nodesel = (cA == 2) ? (w >> 2) : 0;
                int wi = (cA == 2) ? (w & 3) : w;
                int dr = 256 / chunks, d0 = wi * dr;
                int loc = g_lnode[b][pb + nodesel];
                const float* hv = g_h + (size_t)((b << 7) + loc) * 256;
                float a0 = 0, a1 = 0;
#pragma unroll 8
                for (int dd = 0; dd < dr; dd += 2) {
                    int d = d0 + dd;
                    a0 = fmaf(hv[d], Wfh[d * 256 + ch], a0);
                    a1 = fmaf(hv[d + 1], Wfh[(d + 1) * 256 + ch], a1);
                }
                sparta[nodesel * 256 + wi * 32 + l] = a0 + a1;
                __syncthreads();
                if (w < cA) {
                    float a = 0;
                    for (int k = 0; k < chunks; k++) a += sparta[w * 256 + k * 32 + l];
                    swfhh[g_lnode[b][pb + w] * 32 + l] = a;
                }
            }
            __syncthreads();

            // ===== phase B: commit height-L nodes =====
            int nbeg = g_loff[b][L], nend = g_loff[b][L + 1];
            int cB = nend - nbeg;
            if (cB > 3) {
                // warp-per-node
                for (int li = nbeg + w; li < nend; li += 8) {
                    int loc = g_lnode[b][li];
                    int n = (b << 7) + loc;
                    int beg = g_coff[b][loc], end = g_coff[b][loc + 1];
                    float r[8];
#pragma unroll
                    for (int k = 0; k < 8; k++) r[k] = 0.0f;
                    for (int e = beg; e < end; e++) {
                        const float* hc = g_h + (size_t)((b << 7) + g_cch[b][e]) * 256;
#pragma unroll
                        for (int k = 0; k < 8; k++) r[k] += hc[l + 32 * k];
                    }
#pragma unroll
                    for (int k = 0; k < 8; k++) shw[l + 32 * k] = r[k];
                    __syncwarp();
                    float i0 = 0, i1 = 0, o0 = 0, o1 = 0, u0 = 0, u1 = 0;
#pragma unroll 4
                    for (int d = 0; d < 256; d += 2) {
                        float h0 = shw[d], h1 = shw[d + 1];
                        i0 = fmaf(h0, Wih[d * 256 + ch], i0);
                        o0 = fmaf(h0, Woh[d * 256 + ch], o0);
                        u0 = fmaf(h0, Wuh[d * 256 + ch], u0);
                        i1 = fmaf(h1, Wih[(d + 1) * 256 + ch], i1);
                        o1 = fmaf(h1, Woh[(d + 1) * 256 + ch], o1);
                        u1 = fmaf(h1, Wuh[(d + 1) * 256 + ch], u1);
                    }
                    const float* pr = g_proj + (size_t)n * 1024;
                    float fxv = pr[256 + ch];
                    float fc = 0.0f;
                    for (int e = beg; e < end; e++) {
                        int cl = g_cch[b][e];
                        fc = fmaf(sg(swfhh[cl * 32 + l] + fxv),
                                  g_c[(size_t)((b << 7) + cl) * 256 + ch], fc);
                    }
                    float ig = sg(pr[ch] + i0 + i1);
                    float og = sg(pr[512 + ch] + o0 + o1);
                    float ug = tanhf(pr[768 + ch] + u0 + u1);
                    float cc = fmaf(ig, ug, fc);
                    g_c[(size_t)n * 256 + ch] = cc;
                    g_h[(size_t)n * 256 + ch] = og * tanhf(cc);
                    __syncwarp();
                }
            } else {
                // narrow: whole CTA per node, d split over warps
                for (int ni = nbeg; ni < nend; ni++) {
                    int loc = g_lnode[b][ni];
                    int n = (b << 7) + loc;
                    int beg = g_coff[b][loc], end = g_coff[b][loc + 1];
                    float s = 0.0f;
                    for (int e = beg; e < end; e++)
                        s += g_h[(size_t)((b << 7) + g_cch[b][e]) * 256 + tid];
                    hsum[tid] = s;
                    __syncthreads();
                    float ai = 0, ao = 0, au = 0;
                    int d0 = w * 32;
#pragma unroll 8
                    for (int dd = 0; dd < 32; dd++) {
                        int d = d0 + dd;
                        float hv = hsum[d];
                        ai = fmaf(hv, Wih[d * 256 + ch], ai);
                        ao = fmaf(hv, Woh[d * 256 + ch], ao);
                        au = fmaf(hv, Wuh[d * 256 + ch], au);
                    }
                    spart[w * 32 + l] = ai;
                    spart[256 + w * 32 + l] = ao;
                    spart[512 + w * 32 + l] = au;
                    __syncthreads();
                    if (w == 0) {
                        float si = 0, so = 0, su = 0;
#pragma unroll
                        for (int ww = 0; ww < 8; ww++) {
                            si += spart[ww * 32 + l];
                            so += spart[256 + ww * 32 + l];
                            su += spart[512 + ww * 32 + l];
                        }
                        const float* pr = g_proj + (size_t)n * 1024;
                        float fxv = pr[256 + ch];
                        float fc = 0.0f;
                        for (int e = beg; e < end; e++) {
                            int cl = g_cch[b][e];
                            fc = fmaf(sg(swfhh[cl * 32 + l] + fxv),
                                      g_c[(size_t)((b << 7) + cl) * 256 + ch], fc);
                        }
                        float ig = sg(pr[ch] + si);
                        float og = sg(pr[512 + ch] + so);
                        float ug = tanhf(pr[768 + ch] + su);
                        float cc = fmaf(ig, ug, fc);
                        g_c[(size_t)n * 256 + ch] = cc;
                        g_h[(size_t)n * 256 + ch] = og * tanhf(cc);
                    }
                    __syncthreads();
                }
            }
            __syncthreads();
            if (tid == 0) { bar_sig(&g_tbar[b][L]); bar_spin(&g_tbar[b][L], 8u); }
            __syncthreads();
        }

        // ----- fused max-pool + output projection (CTA q==0) -----
        if (q == 0) {
            float m = -1e30f;
            const float* hp = g_h + (size_t)(b << 7) * 256 + tid;
#pragma unroll 4
            for (int s = 0; s < 128; s++) m = fmaxf(m, hp[s * 256]);
            sm[tid] = m;
            __syncthreads();
            if (tid < LOUT) {
                float a = bout[tid];
#pragma unroll 8
                for (int d = 0; d < 256; d++) a = fmaf(sm[d], Wout[d * LOUT + tid], a);
                out[b * LOUT + tid] = a;
            }
        }
    }
}

extern "C" void kernel_launch(void* const* d_in, const int* in_sizes, int n_in,
                              void* d_out, int out_size) {
    const int* xs     = (const int*)d_in[0];
    const int* rels   = (const int*)d_in[1];
    const int* parent = (const int*)d_in[3];
    const int* height = (const int*)d_in[4];
    int base = (in_sizes[5] == 1) ? 6 : 5;
    const float* embW = (const float*)d_in[base + 0];
    const float* relW = (const float*)d_in[base + 1];
    const float* Wix  = (const float*)d_in[base + 2];
    const float* bix  = (const float*)d_in[base + 3];
    const float* Wih  = (const float*)d_in[base + 4];
    const float* bih  = (const float*)d_in[base + 5];
    const float* Wfx  = (const float*)d_in[base + 6];
    const float* bfx  = (const float*)d_in[base + 7];
    const float* Wfh  = (const float*)d_in[base + 8];
    const float* bfh  = (const float*)d_in[base + 9];
    const float* Wox  = (const float*)d_in[base + 10];
    const float* Woh  = (const float*)d_in[base + 11];
    const float* Wux  = (const float*)d_in[base + 12];
    const float* Wuh  = (const float*)d_in[base + 13];
    const float* Wout = (const float*)d_in[base + 14];
    const float* bout = (const float*)d_in[base + 15];
    float* out = (float*)d_out;

    k_zero<<<1, 512>>>();
    k_main<<<GRID, 256>>>(xs, rels, parent, height, embW, relW,
                          Wix, bix, Wih, bih, Wfx, bfx, Wfh, bfh,
                          Wox, Woh, Wux, Wuh, Wout, bout, out);
}

// round 15
// speedup vs baseline: 2.2576x; 1.2780x over previous
#include <cuda_runtime.h>
#include <math.h>

#define NB   16
#define SL   128
#define NN   2048
#define HH   256
#define LOUT 12
#define NLEV 21
#define GRID 128

// ---- dynamic smem layout (float offsets) ----
#define OFF_W      0         // [4][256][32] weight slices (Wih,Woh,Wuh,Wfh) = 32768
#define OFF_SWFHH  32768     // [128][32] per-node Wfh·h slice               = 4096
#define OFF_SHB    36864     // 8 warps x 1024: batch staging / GEMM / setup = 8192
#define OFF_HSUM   45056     // [256]
#define OFF_SPART  45312     // [3][256]
#define OFF_SPARTA 46080     // [8][64]
#define SMEM_FLOATS 46592
#define SMEM_BYTES (SMEM_FLOATS * 4)

__device__ float g_x[NN * 256];
__device__ float g_proj[NN * 1024];
__device__ float g_h[NN * 256];
__device__ float g_c[NN * 256];
__device__ int   g_coff[NB][SL + 1];
__device__ int   g_cch[NB][SL];
__device__ int   g_loff[NB][NLEV + 2];
__device__ int   g_lnode[NB][SL];
__device__ unsigned g_tbar[NB][NLEV + 1];
__device__ unsigned g_gbar[4];

__device__ __forceinline__ float sg(float v) { return 1.0f / (1.0f + __expf(-v)); }

__device__ __forceinline__ void bar_sig(unsigned* p) {
    unsigned long long ga;
    asm("cvta.to.global.u64 %0, %1;" : "=l"(ga) : "l"(p));
    asm volatile("red.release.gpu.global.add.u32 [%0], 1;" :: "l"(ga) : "memory");
}
__device__ __forceinline__ void bar_spin(unsigned* p, unsigned tgt) {
    unsigned long long ga;
    asm("cvta.to.global.u64 %0, %1;" : "=l"(ga) : "l"(p));
    unsigned v;
    do {
        asm volatile("ld.acquire.gpu.global.u32 %0, [%1];" : "=r"(v) : "l"(ga) : "memory");
    } while (v < tgt);
}

__global__ void k_zero() {
    int t = threadIdx.x;
    if (t < NB * (NLEV + 1)) ((unsigned*)g_tbar)[t] = 0u;
    if (t < 4) g_gbar[t] = 0u;
}

__global__ void __launch_bounds__(256, 1) k_main(
    const int* __restrict__ xs, const int* __restrict__ rels,
    const int* __restrict__ parent, const int* __restrict__ height,
    const float* __restrict__ embW, const float* __restrict__ relW,
    const float* __restrict__ Wix, const float* __restrict__ bix,
    const float* __restrict__ Wih, const float* __restrict__ bih,
    const float* __restrict__ Wfx, const float* __restrict__ bfx,
    const float* __restrict__ Wfh, const float* __restrict__ bfh,
    const float* __restrict__ Wox, const float* __restrict__ Woh,
    const float* __restrict__ Wux, const float* __restrict__ Wuh,
    const float* __restrict__ Wout, const float* __restrict__ bout,
    float* __restrict__ out)
{
    extern __shared__ float smd[];
    int tid = threadIdx.x;
    int bx = blockIdx.x;
    int ch0 = (bx & 7) * 32;

    // ========== phase 1: gather x = concat(emb[xs], rel[rels]) ==========
    for (int idx = tid; idx < 16 * 256; idx += 256) {
        int nl = idx >> 8, d = idx & 255;
        int n = bx * 16 + nl;
        float v = (d < 192) ? embW[(long long)xs[n] * 192 + d]
                            : relW[(long long)rels[n] * 64 + (d - 192)];
        g_x[n * 256 + d] = v;
    }

    // ========== phase 1.5: preload this CTA's weight slices into smem ==========
    {
        for (int idx = tid; idx < 4 * 256 * 32; idx += 256) {
            int m = idx >> 13, d = (idx >> 5) & 255, l = idx & 31;
            const float* W = (m == 0) ? Wih : (m == 1) ? Woh : (m == 2) ? Wuh : Wfh;
            smd[OFF_W + idx] = W[d * 256 + ch0 + l];
        }
    }

    // ========== phase 2: setup (CTAs 0..15, deterministic) ==========
    if (bx < NB) {
        int b = bx;
        int* spar  = (int*)(smd + OFF_SHB);   // [128]
        int* shgt  = spar + 128;              // [128]
        int* soff  = shgt + 128;              // [129]
        int* sloff = soff + 129;              // [23]
        if (tid < 127) spar[tid] = parent[b * 127 + tid] - b * 128;
        if (tid < 128) shgt[tid] = height[b * 128 + tid];
        __syncthreads();
        if (tid < 128) {
            int d = 0;
            for (int e = 0; e < 127; e++) d += (spar[e] == tid);
            soff[tid] = d;
        }
        __syncthreads();
        if (tid == 0) {
            int acc = 0;
            for (int i = 0; i < 128; i++) {
                int d = soff[i]; soff[i] = acc; g_coff[b][i] = acc; acc += d;
            }
            soff[128] = acc; g_coff[b][128] = acc;
        }
        __syncthreads();
        if (tid < 128) {
            int k = soff[tid];
            for (int e = 0; e < 127; e++)
                if (spar[e] == tid) g_cch[b][k++] = e + 1;
        }
        if (tid <= NLEV) {
            int c = 0;
            for (int i = 0; i < 128; i++) c += (shgt[i] == tid);
            sloff[tid] = c;
        }
        __syncthreads();
        if (tid == 0) {
            int acc = 0;
            for (int l = 0; l <= NLEV; l++) {
                int c = sloff[l]; sloff[l] = acc; g_loff[b][l] = acc; acc += c;
            }
            g_loff[b][NLEV + 1] = acc;
        }
        __syncthreads();
        if (tid < 128) {
            int h = shgt[tid];
            int rank = 0;
            for (int i = 0; i < tid; i++) rank += (shgt[i] == h);
            g_lnode[b][sloff[h] + rank] = tid;
        }
    }
    // ---- grid barrier 0 ----
    __syncthreads();
    if (tid == 0) { bar_sig(&g_gbar[0]); bar_spin(&g_gbar[0], GRID); }
    __syncthreads();

    // ========== phase 3: projections GEMM ==========
    {
        float* As = smd + OFF_SHB;   // [16][65]
        float* Bs = As + 16 * 65;    // [16][64]
        int tx = tid & 15, ty = tid >> 4;
        for (int tile = bx; tile < 512; tile += GRID) {
            int n0 = (tile & 31) * 64;
            int j0 = (tile >> 5) * 64;
            int m = j0 >> 8, h0 = j0 & 255;
            const float* W = (m == 0) ? Wix : (m == 1) ? Wfx : (m == 2) ? Wox : Wux;
            float acc[4][4];
#pragma unroll
            for (int i = 0; i < 4; i++)
#pragma unroll
                for (int j = 0; j < 4; j++) acc[i][j] = 0.0f;
            for (int k0 = 0; k0 < 256; k0 += 16) {
                for (int e = tid; e < 1024; e += 256) {
                    int nl = e >> 4, kk = e & 15;
                    As[kk * 65 + nl] = g_x[(n0 + nl) * 256 + k0 + kk];
                }
                for (int e = tid; e < 1024; e += 256) {
                    int kk = e >> 6, c = e & 63;
                    Bs[kk * 64 + c] = W[(k0 + kk) * 256 + h0 + c];
                }
                __syncthreads();
#pragma unroll
                for (int kk = 0; kk < 16; kk++) {
                    float a0 = As[kk * 65 + tx * 4 + 0], a1 = As[kk * 65 + tx * 4 + 1];
                    float a2 = As[kk * 65 + tx * 4 + 2], a3 = As[kk * 65 + tx * 4 + 3];
                    float b0 = Bs[kk * 64 + ty * 4 + 0], b1 = Bs[kk * 64 + ty * 4 + 1];
                    float b2 = Bs[kk * 64 + ty * 4 + 2], b3 = Bs[kk * 64 + ty * 4 + 3];
                    acc[0][0] += a0 * b0; acc[0][1] += a0 * b1; acc[0][2] += a0 * b2; acc[0][3] += a0 * b3;
                    acc[1][0] += a1 * b0; acc[1][1] += a1 * b1; acc[1][2] += a1 * b2; acc[1][3] += a1 * b3;
                    acc[2][0] += a2 * b0; acc[2][1] += a2 * b1; acc[2][2] += a2 * b2; acc[2][3] += a2 * b3;
                    acc[3][0] += a3 * b0; acc[3][1] += a3 * b1; acc[3][2] += a3 * b2; acc[3][3] += a3 * b3;
                }
                __syncthreads();
            }
#pragma unroll
            for (int jj = 0; jj < 4; jj++) {
                int h = h0 + ty * 4 + jj;
                float bias = (m == 0) ? (bix[h] + bih[h]) : (m == 1) ? (bfx[h] + bfh[h]) : 0.0f;
                int j = j0 + ty * 4 + jj;
#pragma unroll
                for (int i = 0; i < 4; i++)
                    g_proj[(n0 + tx * 4 + i) * 1024 + j] = acc[i][jj] + bias;
            }
        }
    }
    // ---- grid barrier 1 ----
    __syncthreads();
    if (tid == 0) { bar_sig(&g_gbar[1]); bar_spin(&g_gbar[1], GRID); }
    __syncthreads();

    // ========== phase 4: tree LSTM (8 CTAs/tree, 32 channels each) ==========
    {
        int b = bx >> 3;
        int w = tid >> 5, l = tid & 31;
        int ch = ch0 + l;
        int base = b << 7;
        float* sWi   = smd + OFF_W;              // [256][32]
        float* sWo   = smd + OFF_W + 8192;
        float* sWu   = smd + OFF_W + 16384;
        float* sWf   = smd + OFF_W + 24576;
        float* swfhh = smd + OFF_SWFHH;
        float* shb   = smd + OFF_SHB + w * 1024; // per-warp [256][4]
        float* hsum  = smd + OFF_HSUM;
        float* spart = smd + OFF_SPART;
        float* sparta = smd + OFF_SPARTA;

        int Lmax = 20;
        while (Lmax > 1 && g_loff[b][Lmax + 1] == g_loff[b][Lmax]) Lmax--;

        // ----- level 0: leaves (elementwise) -----
        {
            int lb = g_loff[b][0], le = g_loff[b][1];
            for (int li = lb + w; li < le; li += 8) {
                int n = base + g_lnode[b][li];
                const float* pr = g_proj + (size_t)n * 1024;
                float i = sg(pr[ch]), o = sg(pr[512 + ch]), u = tanhf(pr[768 + ch]);
                float c = i * u;
                g_c[(size_t)n * 256 + ch] = c;
                g_h[(size_t)n * 256 + ch] = o * tanhf(c);
            }
        }
        __syncthreads();
        if (tid == 0) { bar_sig(&g_tbar[b][0]); bar_spin(&g_tbar[b][0], 8u); }
        __syncthreads();

        for (int L = 1; L <= Lmax; L++) {
            // ===== phase A: Wfh·h for nodes committed at L-1 =====
            int pb = g_loff[b][L - 1], pe = g_loff[b][L];
            int cA = pe - pb;
            if (cA >= 8) {
                // batched: warp takes groups of 4, weights loaded once per group
                for (int li0 = pb + w * 4; li0 < pe; li0 += 32) {
                    int gs = pe - li0; if (gs > 4) gs = 4;
#pragma unroll 4
                    for (int j = 0; j < 4; j++) {
                        if (j < gs) {
                            const float* hv = g_h + (size_t)(base + g_lnode[b][li0 + j]) * 256;
#pragma unroll
                            for (int k = 0; k < 8; k++)
                                shb[(l + 32 * k) * 4 + j] = hv[l + 32 * k];
                        }
                    }
                    __syncwarp();
                    float a0 = 0, a1 = 0, a2 = 0, a3 = 0;
                    const float4* hb = (const float4*)shb;
#pragma unroll 4
                    for (int d = 0; d < 256; d++) {
                        float4 h4 = hb[d];
                        float wv = sWf[d * 32 + l];
                        a0 = fmaf(h4.x, wv, a0); a1 = fmaf(h4.y, wv, a1);
                        a2 = fmaf(h4.z, wv, a2); a3 = fmaf(h4.w, wv, a3);
                    }
                    float av[4] = {a0, a1, a2, a3};
                    for (int j = 0; j < gs; j++)
                        swfhh[g_lnode[b][li0 + j] * 32 + l] = av[j];
                    __syncwarp();
                }
            } else if (cA > 0) {
                // narrow: tasks = (node, d-half) across 8 warps
                int tasks = cA * 2;
                for (int t = w; t < tasks; t += 8) {
                    int node = t >> 1, half = t & 1;
                    int loc = g_lnode[b][pb + node];
                    const float* hv = g_h + (size_t)(base + loc) * 256 + half * 128;
                    const float* wf = sWf + half * 128 * 32;
                    float a0 = 0, a1 = 0;
#pragma unroll 8
                    for (int dd = 0; dd < 128; dd += 2) {
                        a0 = fmaf(hv[dd], wf[dd * 32 + l], a0);
                        a1 = fmaf(hv[dd + 1], wf[(dd + 1) * 32 + l], a1);
                    }
                    sparta[node * 64 + half * 32 + l] = a0 + a1;
                }
                __syncthreads();
                if (w < cA)
                    swfhh[g_lnode[b][pb + w] * 32 + l] =
                        sparta[w * 64 + l] + sparta[w * 64 + 32 + l];
            }
            __syncthreads();

            // ===== phase B: commit height-L nodes =====
            int nbeg = g_loff[b][L], nend = g_loff[b][L + 1];
            int cB = nend - nbeg;
            if (cB >= 9) {
                // batched: warp takes groups of 4 nodes
                for (int li0 = nbeg + w * 4; li0 < nend; li0 += 32) {
                    int gs = nend - li0; if (gs > 4) gs = 4;
                    for (int j = 0; j < gs; j++) {
                        int loc = g_lnode[b][li0 + j];
                        int beg = g_coff[b][loc], end = g_coff[b][loc + 1];
                        float r[8];
#pragma unroll
                        for (int k = 0; k < 8; k++) r[k] = 0.0f;
                        for (int e = beg; e < end; e++) {
                            const float* hc = g_h + (size_t)(base + g_cch[b][e]) * 256;
#pragma unroll
                            for (int k = 0; k < 8; k++) r[k] += hc[l + 32 * k];
                        }
#pragma unroll
                        for (int k = 0; k < 8; k++)
                            shb[(l + 32 * k) * 4 + j] = r[k];
                    }
                    __syncwarp();
                    float ai[4] = {0, 0, 0, 0}, ao[4] = {0, 0, 0, 0}, au[4] = {0, 0, 0, 0};
                    const float4* hb = (const float4*)shb;
#pragma unroll 2
                    for (int d = 0; d < 256; d++) {
                        float4 h4 = hb[d];
                        float wi = sWi[d * 32 + l];
                        float wo = sWo[d * 32 + l];
                        float wu = sWu[d * 32 + l];
                        ai[0] = fmaf(h4.x, wi, ai[0]); ao[0] = fmaf(h4.x, wo, ao[0]); au[0] = fmaf(h4.x, wu, au[0]);
                        ai[1] = fmaf(h4.y, wi, ai[1]); ao[1] = fmaf(h4.y, wo, ao[1]); au[1] = fmaf(h4.y, wu, au[1]);
                        ai[2] = fmaf(h4.z, wi, ai[2]); ao[2] = fmaf(h4.z, wo, ao[2]); au[2] = fmaf(h4.z, wu, au[2]);
                        ai[3] = fmaf(h4.w, wi, ai[3]); ao[3] = fmaf(h4.w, wo, ao[3]); au[3] = fmaf(h4.w, wu, au[3]);
                    }
                    for (int j = 0; j < gs; j++) {
                        int loc = g_lnode[b][li0 + j];
                        int n = base + loc;
                        int beg = g_coff[b][loc], end = g_coff[b][loc + 1];
                        const float* pr = g_proj + (size_t)n * 1024;
                        float fxv = pr[256 + ch];
                        float fc = 0.0f;
                        for (int e = beg; e < end; e++) {
                            int cl = g_cch[b][e];
                            fc = fmaf(sg(swfhh[cl * 32 + l] + fxv),
                                      g_c[(size_t)(base + cl) * 256 + ch], fc);
                        }
                        float ig = sg(pr[ch] + ai[j]);
                        float og = sg(pr[512 + ch] + ao[j]);
                        float ug = tanhf(pr[768 + ch] + au[j]);
                        float cc = fmaf(ig, ug, fc);
                        g_c[(size_t)n * 256 + ch] = cc;
                        g_h[(size_t)n * 256 + ch] = og * tanhf(cc);
                    }
                    __syncwarp();
                }
            } else {
                // narrow: whole CTA per node, d split over warps, LDS weights
                for (int ni = nbeg; ni < nend; ni++) {
                    int loc = g_lnode[b][ni];
                    int n = base + loc;
                    int beg = g_coff[b][loc], end = g_coff[b][loc + 1];
                    float s = 0.0f;
                    for (int e = beg; e < end; e++)
                        s += g_h[(size_t)(base + g_cch[b][e]) * 256 + tid];
                    hsum[tid] = s;
                    __syncthreads();
                    float ai = 0, ao = 0, au = 0;
                    int d0 = w * 32;
#pragma unroll 8
                    for (int dd = 0; dd < 32; dd++) {
                        int d = d0 + dd;
                        float hv = hsum[d];
                        ai = fmaf(hv, sWi[d * 32 + l], ai);
                        ao = fmaf(hv, sWo[d * 32 + l], ao);
                        au = fmaf(hv, sWu[d * 32 + l], au);
                    }
                    spart[w * 32 + l] = ai;
                    spart[256 + w * 32 + l] = ao;
                    spart[512 + w * 32 + l] = au;
                    __syncthreads();
                    if (w == 0) {
                        float si = 0, so = 0, su = 0;
#pragma unroll
                        for (int ww = 0; ww < 8; ww++) {
                            si += spart[ww * 32 + l];
                            so += spart[256 + ww * 32 + l];
                            su += spart[512 + ww * 32 + l];
                        }
                        const float* pr = g_proj + (size_t)n * 1024;
                        float fxv = pr[256 + ch];
                        float fc = 0.0f;
                        for (int e = beg; e < end; e++) {
                            int cl = g_cch[b][e];
                            fc = fmaf(sg(swfhh[cl * 32 + l] + fxv),
                                      g_c[(size_t)(base + cl) * 256 + ch], fc);
                        }
                        float ig = sg(pr[ch] + si);
                        float og = sg(pr[512 + ch] + so);
                        float ug = tanhf(pr[768 + ch] + su);
                        float cc = fmaf(ig, ug, fc);
                        g_c[(size_t)n * 256 + ch] = cc;
                        g_h[(size_t)n * 256 + ch] = og * tanhf(cc);
                    }
                    __syncthreads();
                }
            }
            __syncthreads();
            if (tid == 0) { bar_sig(&g_tbar[b][L]); bar_spin(&g_tbar[b][L], 8u); }
            __syncthreads();
        }

        // ----- fused max-pool + output projection (CTA q==0) -----
        if ((bx & 7) == 0) {
            float m = -1e30f;
            const float* hp = g_h + (size_t)base * 256 + tid;
#pragma unroll 4
            for (int s = 0; s < 128; s++) m = fmaxf(m, hp[s * 256]);
            hsum[tid] = m;
            __syncthreads();
            if (tid < LOUT) {
                float a = bout[tid];
#pragma unroll 8
                for (int d = 0; d < 256; d++) a = fmaf(hsum[d], Wout[d * LOUT + tid], a);
                out[b * LOUT + tid] = a;
            }
        }
    }
}

extern "C" void kernel_launch(void* const* d_in, const int* in_sizes, int n_in,
                              void* d_out, int out_size) {
    const int* xs     = (const int*)d_in[0];
    const int* rels   = (const int*)d_in[1];
    const int* parent = (const int*)d_in[3];
    const int* height = (const int*)d_in[4];
    int base = (in_sizes[5] == 1) ? 6 : 5;
    const float* embW = (const float*)d_in[base + 0];
    const float* relW = (const float*)d_in[base + 1];
    const float* Wix  = (const float*)d_in[base + 2];
    const float* bix  = (const float*)d_in[base + 3];
    const float* Wih  = (const float*)d_in[base + 4];
    const float* bih  = (const float*)d_in[base + 5];
    const float* Wfx  = (const float*)d_in[base + 6];
    const float* bfx  = (const float*)d_in[base + 7];
    const float* Wfh  = (const float*)d_in[base + 8];
    const float* bfh  = (const float*)d_in[base + 9];
    const float* Wox  = (const float*)d_in[base + 10];
    const float* Woh  = (const float*)d_in[base + 11];
    const float* Wux  = (const float*)d_in[base + 12];
    const float* Wuh  = (const float*)d_in[base + 13];
    const float* Wout = (const float*)d_in[base + 14];
    const float* bout = (const float*)d_in[base + 15];
    float* out = (float*)d_out;

    static int smem_set = 0;
    if (!smem_set) {
        cudaFuncSetAttribute(k_main, cudaFuncAttributeMaxDynamicSharedMemorySize, SMEM_BYTES);
        smem_set = 1;
    }

    k_zero<<<1, 512>>>();
    k_main<<<GRID, 256, SMEM_BYTES>>>(xs, rels, parent, height, embW, relW,
                                      Wix, bix, Wih, bih, Wfx, bfx, Wfh, bfh,
                                      Wox, Woh, Wux, Wuh, Wout, bout, out);
}